// round 1
// baseline (speedup 1.0000x reference)
#include <cuda_runtime.h>
#include <math_constants.h>

// ----------------------------------------------------------------------------
// Window VQ: for each 128-dim window of ze, argmin_k ||z - c_k||^2 over a
// 2048x128 codebook, then emit the winning codebook row.
//
// argmin ||z-c||^2  ==  argmax ( z.c - 0.5*||c||^2 )
//
// Exact fp32 arithmetic (FFMA), using packed fma.rn.f32x2 (SASS FFMA2) to
// reach the full 128 FMA/SM/cyc fp32 rate on sm_100a.
// ----------------------------------------------------------------------------

#define D       128     // window / codebook dim
#define BM      64      // windows per block
#define BN      64      // codebook entries per n-tile
#define BKC     64      // k-chunk for B staging
#define NTHR    256

__device__ float g_cnorm[4096];   // 0.5*||c_k||^2  (K <= 4096)

// ---------------------------------------------------------------------------
// 0.5 * ||c||^2 per codebook row. One warp per row.
// ---------------------------------------------------------------------------
__global__ void cnorm_kernel(const float* __restrict__ cb, int K) {
    int row  = blockIdx.x * 8 + (threadIdx.x >> 5);
    int lane = threadIdx.x & 31;
    if (row < K) {
        const float4 v = reinterpret_cast<const float4*>(cb + (size_t)row * D)[lane];
        float s = v.x * v.x + v.y * v.y + v.z * v.z + v.w * v.w;
        #pragma unroll
        for (int o = 16; o; o >>= 1) s += __shfl_xor_sync(0xffffffffu, s, o);
        if (lane == 0) g_cnorm[row] = 0.5f * s;
    }
}

// Swizzled k-major smem word index for element (k, r), r in [0,64).
// 16B-chunk index (r>>2) is XORed with (k&15): conflict-free LDS.128 in the
// hot loop (lanes vary r-chunk at fixed k) AND conflict-free STS.32 staging
// with the 4-rows x 8-k lane mapping used below.
__device__ __forceinline__ int swz(int k, int r) {
    return (k << 6) + ((((r >> 2) ^ (k & 15)) << 2) | (r & 3));
}

__device__ __forceinline__ float u2f_lo(unsigned long long a) {
    return __uint_as_float((unsigned)(a & 0xffffffffull));
}
__device__ __forceinline__ float u2f_hi(unsigned long long a) {
    return __uint_as_float((unsigned)(a >> 32));
}

// ---------------------------------------------------------------------------
// Main fused kernel: GEMM (scores) + argmax + gather.
// Grid: M/64 blocks, 256 threads.
// ---------------------------------------------------------------------------
__global__ __launch_bounds__(NTHR, 2)
void vq_main_kernel(const float* __restrict__ ze,
                    const float* __restrict__ cb,
                    float* __restrict__ out,
                    int K) {
    __shared__ __align__(16) float As[BM * D];    // 32 KB, swizzled k-major
    __shared__ __align__(16) float Bs[BKC * BN];  // 16 KB, swizzled k-major

    const int tid  = threadIdx.x;
    const int tn   = tid & 15;       // n-quad  (entries tn*4 .. tn*4+3)
    const int tm   = tid >> 4;       // m-quad  (windows tm*4 .. tm*4+3)
    const int lane = tid & 31;
    const int wgrp = tid >> 5;

    // ---- stage A (64 windows x 128 dims) into swizzled smem, once ----
    {
        const float* asrc = ze + (size_t)blockIdx.x * (BM * D);
        #pragma unroll
        for (int b = 0; b < 4; ++b) {
            float v[8]; int sa[8];
            #pragma unroll
            for (int u = 0; u < 8; ++u) {
                int g = ((b << 3) + u) * 8 + wgrp;            // 0..255
                int r = (lane & 3) + ((g & 15) << 2);         // 0..63
                int k = (lane >> 2) + ((g >> 4) << 3);        // 0..127
                v[u]  = __ldg(&asrc[r * D + k]);
                sa[u] = swz(k, r);
            }
            #pragma unroll
            for (int u = 0; u < 8; ++u) As[sa[u]] = v[u];
        }
    }
    __syncthreads();

    float best[4] = {-CUDART_INF_F, -CUDART_INF_F, -CUDART_INF_F, -CUDART_INF_F};
    int   bidx[4] = {0, 0, 0, 0};

    const int ntiles = K >> 6;   // 32
    for (int nt = 0; nt < ntiles; ++nt) {
        unsigned long long acc[2][4] = {};   // [m-pair][n] packed f32x2 dots
        const float* bsrc = cb + (size_t)nt * BN * D;

        #pragma unroll
        for (int kc = 0; kc < 2; ++kc) {
            __syncthreads();   // previous use of Bs finished
            // ---- stage B chunk (64 entries x 64 dims) ----
            #pragma unroll
            for (int b = 0; b < 2; ++b) {
                float v[8]; int sa[8];
                #pragma unroll
                for (int u = 0; u < 8; ++u) {
                    int g  = ((b << 3) + u) * 8 + wgrp;       // 0..127
                    int r  = (lane & 3) + ((g & 15) << 2);    // 0..63
                    int kl = (lane >> 2) + ((g >> 4) << 3);   // 0..63
                    v[u]  = __ldg(&bsrc[r * D + (kc << 6) + kl]);
                    sa[u] = swz(kl, r);
                }
                #pragma unroll
                for (int u = 0; u < 8; ++u) Bs[sa[u]] = v[u];
            }
            __syncthreads();

            // ---- compute: 64 k-steps, 8 FFMA2 (=16 FMA) per step ----
            #pragma unroll 16
            for (int kk = 0; kk < BKC; ++kk) {
                const int kA = (kc << 6) + kk;
                const ulonglong2 av = *reinterpret_cast<const ulonglong2*>(
                    &As[(kA << 6) + ((tm ^ (kA & 15)) << 2)]);
                const float4 bv = *reinterpret_cast<const float4*>(
                    &Bs[(kk << 6) + ((tn ^ (kk & 15)) << 2)]);
                unsigned long long b0, b1, b2, b3;
                asm("mov.b64 %0, {%1, %1};" : "=l"(b0) : "r"(__float_as_uint(bv.x)));
                asm("mov.b64 %0, {%1, %1};" : "=l"(b1) : "r"(__float_as_uint(bv.y)));
                asm("mov.b64 %0, {%1, %1};" : "=l"(b2) : "r"(__float_as_uint(bv.z)));
                asm("mov.b64 %0, {%1, %1};" : "=l"(b3) : "r"(__float_as_uint(bv.w)));
                asm("fma.rn.f32x2 %0, %1, %2, %0;" : "+l"(acc[0][0]) : "l"(av.x), "l"(b0));
                asm("fma.rn.f32x2 %0, %1, %2, %0;" : "+l"(acc[0][1]) : "l"(av.x), "l"(b1));
                asm("fma.rn.f32x2 %0, %1, %2, %0;" : "+l"(acc[0][2]) : "l"(av.x), "l"(b2));
                asm("fma.rn.f32x2 %0, %1, %2, %0;" : "+l"(acc[0][3]) : "l"(av.x), "l"(b3));
                asm("fma.rn.f32x2 %0, %1, %2, %0;" : "+l"(acc[1][0]) : "l"(av.y), "l"(b0));
                asm("fma.rn.f32x2 %0, %1, %2, %0;" : "+l"(acc[1][1]) : "l"(av.y), "l"(b1));
                asm("fma.rn.f32x2 %0, %1, %2, %0;" : "+l"(acc[1][2]) : "l"(av.y), "l"(b2));
                asm("fma.rn.f32x2 %0, %1, %2, %0;" : "+l"(acc[1][3]) : "l"(av.y), "l"(b3));
            }
        }

        // ---- scores + running argmax (ascending n => first-max kept) ----
        const int nbase = nt << 6;
        #pragma unroll
        for (int j = 0; j < 4; ++j) {
            const int n = nbase + (tn << 2) + j;
            const float cn = g_cnorm[n];
            #pragma unroll
            for (int p = 0; p < 2; ++p) {
                const unsigned long long a = acc[p][j];
                const float s0 = u2f_lo(a) - cn;
                const float s1 = u2f_hi(a) - cn;
                const int i0 = (p << 1), i1 = i0 + 1;
                if (s0 > best[i0]) { best[i0] = s0; bidx[i0] = n; }
                if (s1 > best[i1]) { best[i1] = s1; bidx[i1] = n; }
            }
        }
    }
    __syncthreads();

    // ---- cross-thread reduction (16 candidates per window), alias onto Bs ----
    float* sred = Bs;                          // 64*16 floats
    int*   sidx = (int*)(Bs + 1024);           // 64*16 ints
    int*   widx = (int*)(Bs + 2048);           // 64 ints
    #pragma unroll
    for (int i = 0; i < 4; ++i) {
        const int m = (tm << 2) + i;
        sred[m * 16 + tn] = best[i];
        sidx[m * 16 + tn] = bidx[i];
    }
    __syncthreads();
    if (tid < 64) {
        float bs = sred[tid * 16];
        int   bi = sidx[tid * 16];
        #pragma unroll
        for (int q = 1; q < 16; ++q) {
            const float s  = sred[tid * 16 + q];
            const int   ix = sidx[tid * 16 + q];
            if (s > bs || (s == bs && ix < bi)) { bs = s; bi = ix; }
        }
        widx[tid] = bi;
    }
    __syncthreads();

    // ---- gather winning codebook rows to output (L2-hot) ----
    const float4* cb4  = reinterpret_cast<const float4*>(cb);
    float4*       out4 = reinterpret_cast<float4*>(out) + (size_t)blockIdx.x * (BM * 32);
    #pragma unroll
    for (int i = 0; i < 8; ++i) {
        const int f = tid + (i << 8);       // 0..2047
        const int w = f >> 5, c = f & 31;
        out4[f] = __ldg(&cb4[(size_t)widx[w] * 32 + c]);
    }
}

// ---------------------------------------------------------------------------
extern "C" void kernel_launch(void* const* d_in, const int* in_sizes, int n_in,
                              void* d_out, int out_size) {
    const float* ze = (const float*)d_in[0];
    const float* cb = (const float*)d_in[1];
    float* out = (float*)d_out;

    const int M = in_sizes[0] / D;   // 65536 windows
    const int K = in_sizes[1] / D;   // 2048 entries

    cnorm_kernel<<<(K + 7) / 8, NTHR>>>(cb, K);
    vq_main_kernel<<<M / BM, NTHR>>>(ze, cb, out, K);
}

// round 2
// speedup vs baseline: 1.2702x; 1.2702x over previous
#include <cuda_runtime.h>
#include <math_constants.h>

// ----------------------------------------------------------------------------
// Window VQ: for each 128-dim window of ze, argmin_k ||z - c_k||^2 over a
// 2048x128 codebook, then emit the winning codebook row.
//   argmin ||z-c||^2  ==  argmax ( z.c - 0.5*||c||^2 )
// Exact fp32 via packed fma.rn.f32x2 (FFMA2): 128 FMA/SM/cyc on sm_100a.
//
// R2: 8x8 register tile (was 4x4) to halve LDS traffic per FMA; A broadcast
// reads; B read as natural f32x2 pairs; double-buffered B staging with
// register prefetch; block tile 64m x 256n, BK=32.
// ----------------------------------------------------------------------------

#define D       128
#define BM      64      // windows per block
#define BNT     256     // codebook entries per n-tile
#define BK      32      // B k-chunk
#define NTHR    256

__device__ float g_cnorm[4096];   // 0.5*||c_k||^2

__global__ void cnorm_kernel(const float* __restrict__ cb, int K) {
    int row  = blockIdx.x * 8 + (threadIdx.x >> 5);
    int lane = threadIdx.x & 31;
    if (row < K) {
        const float4 v = reinterpret_cast<const float4*>(cb + (size_t)row * D)[lane];
        float s = v.x * v.x + v.y * v.y + v.z * v.z + v.w * v.w;
        #pragma unroll
        for (int o = 16; o; o >>= 1) s += __shfl_xor_sync(0xffffffffu, s, o);
        if (lane == 0) g_cnorm[row] = 0.5f * s;
    }
}

#define DUP64(d, f)  asm("mov.b64 %0, {%1, %1};" : "=l"(d) : "r"(__float_as_uint(f)))
#define FMA2(a, x, y) asm("fma.rn.f32x2 %0, %1, %2, %0;" : "+l"(a) : "l"(x), "l"(y))

__device__ __forceinline__ float u2f_lo(unsigned long long a) {
    return __uint_as_float((unsigned)(a & 0xffffffffull));
}
__device__ __forceinline__ float u2f_hi(unsigned long long a) {
    return __uint_as_float((unsigned)(a >> 32));
}

// B chunk staging: 32k x 256n, float4 (k-quad) LDG, swizzled STS.
// Swizzle: n-chunk (n>>2) XORed with k-quad (kk>>2)  -> conflict-free STS and
// optimally-phased LDS in the hot loop.
__device__ __forceinline__ void b_ldg(float4 (&v)[8], const float* __restrict__ cb,
                                      int cc, int lane, int wgrp) {
    const int nt = cc >> 2, kc = cc & 3;
    const float4* src = reinterpret_cast<const float4*>(cb);
    const int kq = lane & 7;
    #pragma unroll
    for (int u = 0; u < 8; ++u) {
        const int n = u * 32 + wgrp * 4 + (lane >> 3);
        v[u] = __ldg(&src[(size_t)(nt * 256 + n) * 32 + kc * 8 + kq]);
    }
}

__device__ __forceinline__ void b_sts(float* __restrict__ buf, const float4 (&v)[8],
                                      int lane, int wgrp) {
    const int kq = lane & 7;
    #pragma unroll
    for (int u = 0; u < 8; ++u) {
        const int n   = u * 32 + wgrp * 4 + (lane >> 3);
        const int nc  = u * 8 + wgrp;                    // n>>2
        const int col = (((nc ^ kq) << 2) | (n & 3));
        buf[(kq * 4 + 0) * 256 + col] = v[u].x;
        buf[(kq * 4 + 1) * 256 + col] = v[u].y;
        buf[(kq * 4 + 2) * 256 + col] = v[u].z;
        buf[(kq * 4 + 3) * 256 + col] = v[u].w;
    }
}

// ---------------------------------------------------------------------------
// Main fused kernel: scores GEMM + argmax + gather. Grid: M/64, 256 threads.
// Dynamic smem: As 32KB | Bs 2x32KB | Cn 8KB  = 104 KB.
// ---------------------------------------------------------------------------
__global__ __launch_bounds__(NTHR, 1)
void vq_main_kernel(const float* __restrict__ ze,
                    const float* __restrict__ cb,
                    float* __restrict__ out,
                    int K) {
    extern __shared__ __align__(16) float sm[];
    float* As = sm;                    // [k 0..127][m 0..63] swizzled, 8192 f
    float* Bs = sm + 8192;             // 2 buffers of [kk 0..31][n 0..255], 8192 f each
    float* Cn = sm + 8192 + 16384;     // 2048 f

    const int tid  = threadIdx.x;
    const int lane = tid & 31;
    const int wgrp = tid >> 5;
    const int tn   = lane;     // n groups: {tn*4..+3} and {128+tn*4..+3}
    const int tm2  = wgrp;     // m groups: {tm2*4..+3} and {32+tm2*4..+3}

    // ---- stage A (64 x 128), float4 LDG + swizzled STS ----
    {
        const float4* zsrc = reinterpret_cast<const float4*>(ze) + (size_t)blockIdx.x * (BM * 32);
        #pragma unroll
        for (int u = 0; u < 2; ++u) {
            const int m  = u * 32 + wgrp * 4 + (lane >> 3);
            const int mc = u * 8 + wgrp;                  // m>>2
            #pragma unroll
            for (int vv = 0; vv < 4; ++vv) {
                const int kq = vv * 8 + (lane & 7);       // 0..31
                const float4 val = __ldg(&zsrc[m * 32 + kq]);
                const int col = (((mc ^ (kq & 15)) << 2) | (m & 3));
                As[(kq * 4 + 0) * 64 + col] = val.x;
                As[(kq * 4 + 1) * 64 + col] = val.y;
                As[(kq * 4 + 2) * 64 + col] = val.z;
                As[(kq * 4 + 3) * 64 + col] = val.w;
            }
        }
    }
    // ---- stage cnorm ----
    for (int i = tid; i < K; i += NTHR) Cn[i] = g_cnorm[i];

    // ---- prologue: stage B chunk 0 ----
    {
        float4 v0[8];
        b_ldg(v0, cb, 0, lane, wgrp);
        b_sts(Bs, v0, lane, wgrp);
    }
    __syncthreads();

    unsigned long long acc[8][4];
    #pragma unroll
    for (int i = 0; i < 8; ++i)
        #pragma unroll
        for (int p = 0; p < 4; ++p) acc[i][p] = 0ull;

    float best[8];
    int   bidx[8];
    #pragma unroll
    for (int i = 0; i < 8; ++i) { best[i] = -CUDART_INF_F; bidx[i] = 0; }

    const int nchunks = K >> 6;   // 32 for K=2048
    for (int cc = 0; cc < nchunks; ++cc) {
        float* Bbuf = Bs + (cc & 1) * 8192;
        float4 vnext[8];
        if (cc + 1 < nchunks) b_ldg(vnext, cb, cc + 1, lane, wgrp);

        const int kc = cc & 3;
        #pragma unroll 2
        for (int kb = 0; kb < 8; ++kb) {                  // k-quads within chunk
            const int sA = ((kc << 3) + kb) & 15;
            const int cA = (tm2 ^ sA) << 2;               // A column offset (words)
            const int cB = (tn ^ kb) << 2;                // B column offset (words)
            #pragma unroll
            for (int ki = 0; ki < 4; ++ki) {
                const int kk = kb * 4 + ki;
                const int k  = (kc << 5) + kk;
                const float4 a0 = *reinterpret_cast<const float4*>(&As[k * 64 + cA]);
                const float4 a1 = *reinterpret_cast<const float4*>(&As[k * 64 + (cA ^ 32)]);
                const ulonglong2 b0 = *reinterpret_cast<const ulonglong2*>(&Bbuf[kk * 256 + cB]);
                const ulonglong2 b1 = *reinterpret_cast<const ulonglong2*>(&Bbuf[kk * 256 + (cB ^ 128)]);
                unsigned long long ad[8];
                DUP64(ad[0], a0.x); DUP64(ad[1], a0.y); DUP64(ad[2], a0.z); DUP64(ad[3], a0.w);
                DUP64(ad[4], a1.x); DUP64(ad[5], a1.y); DUP64(ad[6], a1.z); DUP64(ad[7], a1.w);
                #pragma unroll
                for (int i = 0; i < 8; ++i) {
                    FMA2(acc[i][0], ad[i], b0.x);
                    FMA2(acc[i][1], ad[i], b0.y);
                    FMA2(acc[i][2], ad[i], b1.x);
                    FMA2(acc[i][3], ad[i], b1.y);
                }
            }
        }

        if (cc + 1 < nchunks) b_sts(Bs + ((cc + 1) & 1) * 8192, vnext, lane, wgrp);

        if ((cc & 3) == 3) {
            // full dot products over D done for n-tile nt: score + argmax
            const int nbase = (cc >> 2) << 8;
            #pragma unroll
            for (int i = 0; i < 8; ++i) {
                #pragma unroll
                for (int p = 0; p < 4; ++p) {
                    const int n0 = nbase + tn * 4 + ((p & 2) ? 128 : 0) + ((p & 1) << 1);
                    const float2 cn2 = *reinterpret_cast<const float2*>(&Cn[n0]);
                    const float s0 = u2f_lo(acc[i][p]) - cn2.x;
                    const float s1 = u2f_hi(acc[i][p]) - cn2.y;
                    if (s0 > best[i]) { best[i] = s0; bidx[i] = n0; }
                    if (s1 > best[i]) { best[i] = s1; bidx[i] = n0 + 1; }
                    acc[i][p] = 0ull;
                }
            }
        }
        __syncthreads();
    }

    // ---- cross-thread reduction: 32 candidates per window, alias onto Bs ----
    float* sred = Bs;                      // 64*32 floats
    int*   sidx = (int*)(Bs + 2048);       // 64*32 ints
    int*   widx = (int*)(Bs + 4096);       // 64 ints
    #pragma unroll
    for (int i = 0; i < 8; ++i) {
        const int m = (i < 4) ? (tm2 * 4 + i) : (32 + tm2 * 4 + (i - 4));
        sred[m * 32 + tn] = best[i];
        sidx[m * 32 + tn] = bidx[i];
    }
    __syncthreads();
    if (tid < 64) {
        float bs = sred[tid * 32];
        int   bi = sidx[tid * 32];
        #pragma unroll
        for (int q = 1; q < 32; ++q) {
            const float s  = sred[tid * 32 + q];
            const int   ix = sidx[tid * 32 + q];
            if (s > bs || (s == bs && ix < bi)) { bs = s; bi = ix; }
        }
        widx[tid] = bi;
    }
    __syncthreads();

    // ---- gather winning codebook rows (L2-hot) ----
    const float4* cb4  = reinterpret_cast<const float4*>(cb);
    float4*       out4 = reinterpret_cast<float4*>(out) + (size_t)blockIdx.x * (BM * 32);
    #pragma unroll
    for (int i = 0; i < 8; ++i) {
        const int f = i * 256 + tid;        // 0..2047
        const int w = f >> 5, c = f & 31;
        out4[f] = __ldg(&cb4[(size_t)widx[w] * 32 + c]);
    }
}

// ---------------------------------------------------------------------------
extern "C" void kernel_launch(void* const* d_in, const int* in_sizes, int n_in,
                              void* d_out, int out_size) {
    const float* ze = (const float*)d_in[0];
    const float* cb = (const float*)d_in[1];
    float* out = (float*)d_out;

    const int M = in_sizes[0] / D;   // 65536 windows
    const int K = in_sizes[1] / D;   // 2048 entries

    const int smem_bytes = (8192 + 16384 + 2048) * (int)sizeof(float);   // 104 KB
    cudaFuncSetAttribute(vq_main_kernel, cudaFuncAttributeMaxDynamicSharedMemorySize,
                         smem_bytes);

    cnorm_kernel<<<(K + 7) / 8, NTHR>>>(cb, K);
    vq_main_kernel<<<M / BM, NTHR, smem_bytes>>>(ze, cb, out, K);
}